// round 2
// baseline (speedup 1.0000x reference)
#include <cuda_runtime.h>
#include <cuda_bf16.h>
#include <cstdint>

#define D_DIM 512
#define F_DIM 256
#define N_MAX 50000

// Scratch: support = concat(ori, aug) rows -> [2N, F]
__device__ float g_support[2ull * N_MAX * F_DIM];

// ---------------------------------------------------------------------------
// GEMM: support[r][f] = sum_d feat[r][d] * W[d][f], r in [0, 2N)
// feat row r: r < N -> feature_ori[r], else feature_aug[r-N]
// 128x128 block tile, BK=8, 8x8 per thread, 256 threads.
// ---------------------------------------------------------------------------
#define BM 128
#define BN 128
#define BK 8
#define TM 8
#define TN 8

__global__ __launch_bounds__(256, 2)
void gemm_kernel(const float* __restrict__ ori, const float* __restrict__ aug,
                 const float* __restrict__ W, int N) {
    __shared__ float As[BK][BM];
    __shared__ float Bs[BK][BN];

    const int block_row = blockIdx.x * BM;
    const int block_col = blockIdx.y * BN;
    const int tid = threadIdx.x;

    // compute-tile coordinates
    const int tr = (tid / (BN / TN)) * TM;   // 0..120 step 8
    const int tc = (tid % (BN / TN)) * TN;   // 0..120 step 8

    // A-load coordinates: 128 rows x 8 k -> 256 float4 (along k)
    const int a_row = tid >> 1;              // 0..127
    const int a_kc  = (tid & 1) * 4;         // 0 or 4
    // B-load coordinates: 8 k-rows x 128 cols -> 256 float4 (along n)
    const int b_kr = tid >> 5;               // 0..7
    const int b_c4 = (tid & 31) * 4;         // 0..124

    const int grow = block_row + a_row;
    const float* arow_ptr = nullptr;
    if (grow < N)            arow_ptr = ori + (size_t)grow * D_DIM;
    else if (grow < 2 * N)   arow_ptr = aug + (size_t)(grow - N) * D_DIM;

    float acc[TM][TN];
    #pragma unroll
    for (int i = 0; i < TM; i++)
        #pragma unroll
        for (int j = 0; j < TN; j++) acc[i][j] = 0.0f;

    for (int k0 = 0; k0 < D_DIM; k0 += BK) {
        float4 av = make_float4(0.f, 0.f, 0.f, 0.f);
        if (arow_ptr) av = *(const float4*)(arow_ptr + k0 + a_kc);
        As[a_kc + 0][a_row] = av.x;
        As[a_kc + 1][a_row] = av.y;
        As[a_kc + 2][a_row] = av.z;
        As[a_kc + 3][a_row] = av.w;

        float4 bv = *(const float4*)(W + (size_t)(k0 + b_kr) * F_DIM + block_col + b_c4);
        *(float4*)&Bs[b_kr][b_c4] = bv;

        __syncthreads();

        #pragma unroll
        for (int k = 0; k < BK; k++) {
            float ar[TM], br[TN];
            #pragma unroll
            for (int i = 0; i < TM; i++) ar[i] = As[k][tr + i];
            #pragma unroll
            for (int j = 0; j < TN; j++) br[j] = Bs[k][tc + j];
            #pragma unroll
            for (int i = 0; i < TM; i++)
                #pragma unroll
                for (int j = 0; j < TN; j++)
                    acc[i][j] = fmaf(ar[i], br[j], acc[i][j]);
        }
        __syncthreads();
    }

    #pragma unroll
    for (int i = 0; i < TM; i++) {
        const int r = block_row + tr + i;
        if (r < 2 * N) {
            float4* dst = (float4*)(g_support + (size_t)r * F_DIM + block_col + tc);
            dst[0] = make_float4(acc[i][0], acc[i][1], acc[i][2], acc[i][3]);
            dst[1] = make_float4(acc[i][4], acc[i][5], acc[i][6], acc[i][7]);
        }
    }
}

// ---------------------------------------------------------------------------
// Zero the output accumulator (d_out is poisoned by harness).
// ---------------------------------------------------------------------------
__global__ void zero_kernel(float4* __restrict__ p, size_t n4) {
    size_t i = (size_t)blockIdx.x * blockDim.x + threadIdx.x;
    size_t stride = (size_t)gridDim.x * blockDim.x;
    float4 z = make_float4(0.f, 0.f, 0.f, 0.f);
    for (; i < n4; i += stride) p[i] = z;
}

// ---------------------------------------------------------------------------
// Scatter: one warp per (edge, branch). out[b][row] += val * support[b][col]
// grid.y = branch (0: ori, 1: aug)
// ---------------------------------------------------------------------------
__global__ __launch_bounds__(256)
void scatter_kernel(const int* __restrict__ erow, const int* __restrict__ ecol,
                    const float* __restrict__ eval_, float* __restrict__ out,
                    int E, int N) {
    const int warp = (blockIdx.x * blockDim.x + threadIdx.x) >> 5;
    const int lane = threadIdx.x & 31;
    if (warp >= E) return;
    const int b = blockIdx.y;

    const int r = erow[warp];
    const int c = ecol[warp];
    const float v = eval_[warp];

    const float4* src = (const float4*)(g_support + ((size_t)b * N + c) * F_DIM);
    float* dst = out + ((size_t)b * N + r) * F_DIM;

    #pragma unroll
    for (int it = 0; it < F_DIM / (32 * 4); it++) {
        const int f4 = lane + it * 32;
        float4 s = __ldg(&src[f4]);
        const int f = f4 * 4;
        atomicAdd(dst + f + 0, v * s.x);
        atomicAdd(dst + f + 1, v * s.y);
        atomicAdd(dst + f + 2, v * s.z);
        atomicAdd(dst + f + 3, v * s.w);
    }
}

// ---------------------------------------------------------------------------
// Finalize: out = relu(out + bias), in place. Vectorized float4.
// total4 = 2*N*F/4; feature index of float4 i is (i % (F/4))*4
// ---------------------------------------------------------------------------
__global__ void finalize_kernel(float4* __restrict__ out, const float* __restrict__ bias,
                                size_t total4) {
    size_t i = (size_t)blockIdx.x * blockDim.x + threadIdx.x;
    size_t stride = (size_t)gridDim.x * blockDim.x;
    for (; i < total4; i += stride) {
        const int f4 = (int)(i & (F_DIM / 4 - 1));
        float4 bv = *(const float4*)(bias + f4 * 4);
        float4 v = out[i];
        v.x = fmaxf(v.x + bv.x, 0.f);
        v.y = fmaxf(v.y + bv.y, 0.f);
        v.z = fmaxf(v.z + bv.z, 0.f);
        v.w = fmaxf(v.w + bv.w, 0.f);
        out[i] = v;
    }
}

extern "C" void kernel_launch(void* const* d_in, const int* in_sizes, int n_in,
                              void* d_out, int out_size) {
    const float* feature_ori = (const float*)d_in[0];
    const float* feature_aug = (const float*)d_in[1];
    const int*   edge_row    = (const int*)d_in[2];
    const int*   edge_col    = (const int*)d_in[3];
    const float* edge_val    = (const float*)d_in[4];
    const float* weight      = (const float*)d_in[5];
    const float* bias        = (const float*)d_in[6];
    float* out = (float*)d_out;

    const int N = in_sizes[0] / D_DIM;   // 50000
    const int E = in_sizes[2];           // 800000

    // 1) GEMM -> g_support [2N, F]
    {
        dim3 grid((2 * N + BM - 1) / BM, F_DIM / BN);
        gemm_kernel<<<grid, 256>>>(feature_ori, feature_aug, weight, N);
    }

    // 2) zero d_out
    {
        size_t n4 = (size_t)2 * N * F_DIM / 4;
        int blocks = 1024;
        zero_kernel<<<blocks, 256>>>((float4*)out, n4);
    }

    // 3) scatter-aggregate with atomics
    {
        const int warps_per_block = 256 / 32;
        dim3 grid((E + warps_per_block - 1) / warps_per_block, 2);
        scatter_kernel<<<grid, 256>>>(edge_row, edge_col, edge_val, out, E, N);
    }

    // 4) bias + relu in place
    {
        size_t total4 = (size_t)2 * N * F_DIM / 4;
        finalize_kernel<<<2048, 256>>>((float4*)out, bias, total4);
    }
}

// round 6
// speedup vs baseline: 1.6891x; 1.6891x over previous
#include <cuda_runtime.h>
#include <cuda_bf16.h>
#include <cstdint>

#define D_DIM 512
#define F_DIM 256
#define N_MAX 50000
#define E_MAX 800000

// Scratch (static device globals — no allocation allowed)
__device__ float g_support[2ull * N_MAX * F_DIM];   // [2N, F]
__device__ int   g_rowptr[N_MAX + 1];
__device__ int   g_deg[N_MAX];
__device__ int   g_cursor[N_MAX];
__device__ int   g_col_sorted[E_MAX];
__device__ float g_val_sorted[E_MAX];

// ---------------------------------------------------------------------------
// GEMM: support[r][f] = sum_d feat[r][d] * W[d][f], r in [0, 2N)
// 128x128 tile, BK=8, 8x8 per thread, 256 threads, double-buffered smem.
// ---------------------------------------------------------------------------
#define BM 128
#define BN 128
#define BK 8
#define TM 8
#define TN 8

__global__ __launch_bounds__(256, 2)
void gemm_kernel(const float* __restrict__ ori, const float* __restrict__ aug,
                 const float* __restrict__ W, int N) {
    __shared__ float As[2][BK][BM];
    __shared__ float Bs[2][BK][BN];

    const int block_row = blockIdx.x * BM;
    const int block_col = blockIdx.y * BN;
    const int tid = threadIdx.x;

    const int tr = (tid / (BN / TN)) * TM;
    const int tc = (tid % (BN / TN)) * TN;

    const int a_row = tid >> 1;
    const int a_kc  = (tid & 1) * 4;
    const int b_kr = tid >> 5;
    const int b_c4 = (tid & 31) * 4;

    const int grow = block_row + a_row;
    const float* arow_ptr = nullptr;
    if (grow < N)            arow_ptr = ori + (size_t)grow * D_DIM;
    else if (grow < 2 * N)   arow_ptr = aug + (size_t)(grow - N) * D_DIM;

    float acc[TM][TN];
    #pragma unroll
    for (int i = 0; i < TM; i++)
        #pragma unroll
        for (int j = 0; j < TN; j++) acc[i][j] = 0.0f;

    // prologue: load k0 = 0 into buffer 0
    float4 av = make_float4(0.f, 0.f, 0.f, 0.f);
    if (arow_ptr) av = *(const float4*)(arow_ptr + a_kc);
    float4 bv = *(const float4*)(W + (size_t)b_kr * F_DIM + block_col + b_c4);
    As[0][a_kc + 0][a_row] = av.x;
    As[0][a_kc + 1][a_row] = av.y;
    As[0][a_kc + 2][a_row] = av.z;
    As[0][a_kc + 3][a_row] = av.w;
    *(float4*)&Bs[0][b_kr][b_c4] = bv;
    __syncthreads();

    int buf = 0;
    for (int k0 = 0; k0 < D_DIM; k0 += BK) {
        const bool has_next = (k0 + BK) < D_DIM;
        // prefetch next K-slice into registers
        if (has_next) {
            av = make_float4(0.f, 0.f, 0.f, 0.f);
            if (arow_ptr) av = *(const float4*)(arow_ptr + k0 + BK + a_kc);
            bv = *(const float4*)(W + (size_t)(k0 + BK + b_kr) * F_DIM + block_col + b_c4);
        }

        // compute from current buffer
        #pragma unroll
        for (int k = 0; k < BK; k++) {
            float ar[TM], br[TN];
            #pragma unroll
            for (int i = 0; i < TM; i++) ar[i] = As[buf][k][tr + i];
            #pragma unroll
            for (int j = 0; j < TN; j++) br[j] = Bs[buf][k][tc + j];
            #pragma unroll
            for (int i = 0; i < TM; i++)
                #pragma unroll
                for (int j = 0; j < TN; j++)
                    acc[i][j] = fmaf(ar[i], br[j], acc[i][j]);
        }

        if (has_next) {
            const int nb = buf ^ 1;
            As[nb][a_kc + 0][a_row] = av.x;
            As[nb][a_kc + 1][a_row] = av.y;
            As[nb][a_kc + 2][a_row] = av.z;
            As[nb][a_kc + 3][a_row] = av.w;
            *(float4*)&Bs[nb][b_kr][b_c4] = bv;
            __syncthreads();
            buf = nb;
        }
    }

    #pragma unroll
    for (int i = 0; i < TM; i++) {
        const int r = block_row + tr + i;
        if (r < 2 * N) {
            float4* dst = (float4*)(g_support + (size_t)r * F_DIM + block_col + tc);
            dst[0] = make_float4(acc[i][0], acc[i][1], acc[i][2], acc[i][3]);
            dst[1] = make_float4(acc[i][4], acc[i][5], acc[i][6], acc[i][7]);
        }
    }
}

// ---------------------------------------------------------------------------
// CSR build
// ---------------------------------------------------------------------------
__global__ void zero_deg_kernel(int N) {
    int i = blockIdx.x * blockDim.x + threadIdx.x;
    if (i < N) g_deg[i] = 0;
}

__global__ void hist_kernel(const int* __restrict__ erow, int E) {
    int e = blockIdx.x * blockDim.x + threadIdx.x;
    if (e < E) atomicAdd(&g_deg[erow[e]], 1);
}

// single-block chunked exclusive scan over g_deg -> g_rowptr, g_cursor
__global__ void scan_kernel(int N) {
    __shared__ int sdata[1024];
    __shared__ int carry;
    const int tid = threadIdx.x;
    if (tid == 0) carry = 0;
    __syncthreads();

    for (int base = 0; base < N; base += 1024) {
        int v = (base + tid < N) ? g_deg[base + tid] : 0;
        sdata[tid] = v;
        __syncthreads();
        // inclusive scan
        #pragma unroll
        for (int off = 1; off < 1024; off <<= 1) {
            int t = (tid >= off) ? sdata[tid - off] : 0;
            __syncthreads();
            sdata[tid] += t;
            __syncthreads();
        }
        int excl = sdata[tid] - v + carry;
        if (base + tid < N) {
            g_rowptr[base + tid] = excl;
            g_cursor[base + tid] = excl;
        }
        __syncthreads();
        if (tid == 1023) carry += sdata[1023];
        __syncthreads();
    }
    if (tid == 0) g_rowptr[N] = carry;
}

__global__ void scatter_sort_kernel(const int* __restrict__ erow,
                                    const int* __restrict__ ecol,
                                    const float* __restrict__ eval_, int E) {
    int e = blockIdx.x * blockDim.x + threadIdx.x;
    if (e >= E) return;
    int r = erow[e];
    int pos = atomicAdd(&g_cursor[r], 1);
    g_col_sorted[pos] = ecol[e];
    g_val_sorted[pos] = eval_[e];
}

// ---------------------------------------------------------------------------
// Aggregate: one block per (row, branch). thread = feature.
// out[b][row][f] = relu(bias[f] + sum_e val[e] * support[b][col[e]][f])
// ---------------------------------------------------------------------------
__global__ __launch_bounds__(256)
void aggregate_kernel(const float* __restrict__ bias, float* __restrict__ out, int N) {
    const int row = blockIdx.x;
    const int b = blockIdx.y;
    const int tid = threadIdx.x;

    const int start = g_rowptr[row];
    const int end   = g_rowptr[row + 1];

    __shared__ int   s_col[256];
    __shared__ float s_val[256];

    float acc = 0.0f;
    const float* sup = g_support + (size_t)b * N * F_DIM;

    for (int base = start; base < end; base += 256) {
        const int n = min(256, end - base);
        if (tid < n) {
            s_col[tid] = g_col_sorted[base + tid];
            s_val[tid] = g_val_sorted[base + tid];
        }
        __syncthreads();
        for (int e = 0; e < n; e++) {
            acc = fmaf(s_val[e], __ldg(sup + (size_t)s_col[e] * F_DIM + tid), acc);
        }
        __syncthreads();
    }

    out[((size_t)b * N + row) * F_DIM + tid] = fmaxf(acc + bias[tid], 0.0f);
}

extern "C" void kernel_launch(void* const* d_in, const int* in_sizes, int n_in,
                              void* d_out, int out_size) {
    const float* feature_ori = (const float*)d_in[0];
    const float* feature_aug = (const float*)d_in[1];
    const int*   edge_row    = (const int*)d_in[2];
    const int*   edge_col    = (const int*)d_in[3];
    const float* edge_val    = (const float*)d_in[4];
    const float* weight      = (const float*)d_in[5];
    const float* bias        = (const float*)d_in[6];
    float* out = (float*)d_out;

    const int N = in_sizes[0] / D_DIM;   // 50000
    const int E = in_sizes[2];           // 800000

    // CSR build (independent of GEMM, same stream so ordering is fine)
    zero_deg_kernel<<<(N + 255) / 256, 256>>>(N);
    hist_kernel<<<(E + 255) / 256, 256>>>(edge_row, E);
    scan_kernel<<<1, 1024>>>(N);
    scatter_sort_kernel<<<(E + 255) / 256, 256>>>(edge_row, edge_col, edge_val, E);

    // GEMM -> g_support [2N, F]
    {
        dim3 grid((2 * N + BM - 1) / BM, F_DIM / BN);
        gemm_kernel<<<grid, 256>>>(feature_ori, feature_aug, weight, N);
    }

    // Aggregate + bias + relu (writes d_out exactly once)
    {
        dim3 grid(N, 2);
        aggregate_kernel<<<grid, 256>>>(bias, out, N);
    }
}

// round 9
// speedup vs baseline: 1.6917x; 1.0015x over previous
#include <cuda_runtime.h>
#include <cuda_bf16.h>
#include <cuda_fp16.h>
#include <mma.h>
#include <cstdint>

using namespace nvcuda;

#define D_DIM 512
#define F_DIM 256
#define N_MAX 50000
#define E_MAX 800000
// rows padded to a multiple of 128 so the last GEMM tile can store unguarded
#define PAD_ROWS 100096

// Scratch (static device globals — no allocation allowed)
__device__ float g_support[(size_t)PAD_ROWS * F_DIM];   // [>=2N, F]
__device__ int   g_rowptr[N_MAX + 1];
__device__ int   g_deg[N_MAX];
__device__ int   g_cursor[N_MAX];
__device__ int   g_col_sorted[E_MAX];
__device__ float g_val_sorted[E_MAX];

// ===========================================================================
// fp16x3 HMMA GEMM: g_support[r][f] = sum_d feat[r][d] * W[d][f]
// r in [0, 2N): r < N -> feature_ori[r], else feature_aug[r-N]
// CTA tile M=128, N=128 (grid.y selects F half), K staged in chunks of 32.
// Each fp32 operand is split x = hi + lo (fp16); accumulate
// hi*hi + hi*lo + lo*hi in fp32 accumulators (wmma m16n16k16).
// ===========================================================================
#define GBM 128
#define GBN 128
#define GBK 32
#define A_LD (GBK + 8)     // halves: 40  (80 B row stride)
#define B_LD (GBN + 8)     // halves: 136 (272 B row stride)

__global__ __launch_bounds__(256)
void gemm_hmma_kernel(const float* __restrict__ ori, const float* __restrict__ aug,
                      const float* __restrict__ W, int N) {
    // [split][...] : split 0 = hi, 1 = lo
    __shared__ __align__(16) __half As[2][GBM * A_LD];
    __shared__ __align__(16) __half Bs[2][GBK * B_LD];

    const int tid = threadIdx.x;
    const int wid = tid >> 5;
    const int block_row = blockIdx.x * GBM;
    const int n0 = blockIdx.y * GBN;

    const int warp_m = wid >> 1;   // 0..3 -> 32-row slice
    const int warp_n = wid & 1;    // 0..1 -> 64-col slice

    wmma::fragment<wmma::accumulator, 16, 16, 16, float> acc[2][4];
    #pragma unroll
    for (int i = 0; i < 2; i++)
        #pragma unroll
        for (int j = 0; j < 4; j++) wmma::fill_fragment(acc[i][j], 0.0f);

    for (int k0 = 0; k0 < D_DIM; k0 += GBK) {
        // ---- stage A tile: 128 rows x 32 k (fp32 -> hi/lo fp16) ----
        #pragma unroll
        for (int q = 0; q < 4; q++) {
            const int idx = tid + q * 256;       // 0..1023 float4 slots
            const int r   = idx >> 3;            // 0..127
            const int c4  = (idx & 7) * 4;       // k offset 0..28
            const int grow = block_row + r;
            float4 v = make_float4(0.f, 0.f, 0.f, 0.f);
            if (grow < N)          v = *(const float4*)(ori + (size_t)grow * D_DIM + k0 + c4);
            else if (grow < 2 * N) v = *(const float4*)(aug + (size_t)(grow - N) * D_DIM + k0 + c4);

            __half hx = __float2half_rn(v.x), hy = __float2half_rn(v.y);
            __half hz = __float2half_rn(v.z), hw = __float2half_rn(v.w);
            __half lx = __float2half_rn(v.x - __half2float(hx));
            __half ly = __float2half_rn(v.y - __half2float(hy));
            __half lz = __float2half_rn(v.z - __half2float(hz));
            __half lw = __float2half_rn(v.w - __half2float(hw));

            const int base = r * A_LD + c4;
            *(__half2*)&As[0][base]     = __halves2half2(hx, hy);
            *(__half2*)&As[0][base + 2] = __halves2half2(hz, hw);
            *(__half2*)&As[1][base]     = __halves2half2(lx, ly);
            *(__half2*)&As[1][base + 2] = __halves2half2(lz, lw);
        }
        // ---- stage B tile: 32 k-rows x 128 n (fp32 -> hi/lo fp16) ----
        #pragma unroll
        for (int q = 0; q < 4; q++) {
            const int idx = tid + q * 256;       // 0..1023
            const int kr  = idx >> 5;            // 0..31
            const int c4  = (idx & 31) * 4;      // 0..124
            float4 v = *(const float4*)(W + (size_t)(k0 + kr) * F_DIM + n0 + c4);

            __half hx = __float2half_rn(v.x), hy = __float2half_rn(v.y);
            __half hz = __float2half_rn(v.z), hw = __float2half_rn(v.w);
            __half lx = __float2half_rn(v.x - __half2float(hx));
            __half ly = __float2half_rn(v.y - __half2float(hy));
            __half lz = __float2half_rn(v.z - __half2float(hz));
            __half lw = __float2half_rn(v.w - __half2float(hw));

            const int base = kr * B_LD + c4;
            *(__half2*)&Bs[0][base]     = __halves2half2(hx, hy);
            *(__half2*)&Bs[0][base + 2] = __halves2half2(hz, hw);
            *(__half2*)&Bs[1][base]     = __halves2half2(lx, ly);
            *(__half2*)&Bs[1][base + 2] = __halves2half2(lz, lw);
        }
        __syncthreads();

        // ---- compute: 3 split combos x 2 k-steps x (2m x 4n) wmma ----
        #pragma unroll
        for (int s = 0; s < 3; s++) {
            const int sa = (s == 2) ? 1 : 0;   // (hi,hi), (hi,lo), (lo,hi)
            const int sb = (s == 1) ? 1 : 0;
            #pragma unroll
            for (int kk = 0; kk < GBK; kk += 16) {
                wmma::fragment<wmma::matrix_a, 16, 16, 16, __half, wmma::row_major> a[2];
                #pragma unroll
                for (int i = 0; i < 2; i++)
                    wmma::load_matrix_sync(a[i],
                        &As[sa][(warp_m * 32 + i * 16) * A_LD + kk], A_LD);
                #pragma unroll
                for (int j = 0; j < 4; j++) {
                    wmma::fragment<wmma::matrix_b, 16, 16, 16, __half, wmma::row_major> b;
                    wmma::load_matrix_sync(b,
                        &Bs[sb][kk * B_LD + warp_n * 64 + j * 16], B_LD);
                    #pragma unroll
                    for (int i = 0; i < 2; i++)
                        wmma::mma_sync(acc[i][j], a[i], b, acc[i][j]);
                }
            }
        }
        __syncthreads();
    }

    // ---- store accumulators (rows padded; no bounds check needed) ----
    #pragma unroll
    for (int i = 0; i < 2; i++) {
        const int r = block_row + warp_m * 32 + i * 16;
        #pragma unroll
        for (int j = 0; j < 4; j++) {
            const int c = n0 + warp_n * 64 + j * 16;
            wmma::store_matrix_sync(g_support + (size_t)r * F_DIM + c,
                                    acc[i][j], F_DIM, wmma::mem_row_major);
        }
    }
}

// ---------------------------------------------------------------------------
// CSR build
// ---------------------------------------------------------------------------
__global__ void zero_deg_kernel(int N) {
    int i = blockIdx.x * blockDim.x + threadIdx.x;
    if (i < N) g_deg[i] = 0;
}

__global__ void hist_kernel(const int* __restrict__ erow, int E) {
    int e = blockIdx.x * blockDim.x + threadIdx.x;
    if (e < E) atomicAdd(&g_deg[erow[e]], 1);
}

__global__ void scan_kernel(int N) {
    __shared__ int sdata[1024];
    __shared__ int carry;
    const int tid = threadIdx.x;
    if (tid == 0) carry = 0;
    __syncthreads();

    for (int base = 0; base < N; base += 1024) {
        int v = (base + tid < N) ? g_deg[base + tid] : 0;
        sdata[tid] = v;
        __syncthreads();
        #pragma unroll
        for (int off = 1; off < 1024; off <<= 1) {
            int t = (tid >= off) ? sdata[tid - off] : 0;
            __syncthreads();
            sdata[tid] += t;
            __syncthreads();
        }
        int excl = sdata[tid] - v + carry;
        if (base + tid < N) {
            g_rowptr[base + tid] = excl;
            g_cursor[base + tid] = excl;
        }
        __syncthreads();
        if (tid == 1023) carry += sdata[1023];
        __syncthreads();
    }
    if (tid == 0) g_rowptr[N] = carry;
}

__global__ void scatter_sort_kernel(const int* __restrict__ erow,
                                    const int* __restrict__ ecol,
                                    const float* __restrict__ eval_, int E) {
    int e = blockIdx.x * blockDim.x + threadIdx.x;
    if (e >= E) return;
    int r = erow[e];
    int pos = atomicAdd(&g_cursor[r], 1);
    g_col_sorted[pos] = ecol[e];
    g_val_sorted[pos] = eval_[e];
}

// ---------------------------------------------------------------------------
// Aggregate: one block per (row, branch). thread = feature.
// out[b][row][f] = relu(bias[f] + sum_e val[e] * support[b][col[e]][f])
// ---------------------------------------------------------------------------
__global__ __launch_bounds__(256)
void aggregate_kernel(const float* __restrict__ bias, float* __restrict__ out, int N) {
    const int row = blockIdx.x;
    const int b = blockIdx.y;
    const int tid = threadIdx.x;

    const int start = g_rowptr[row];
    const int end   = g_rowptr[row + 1];

    __shared__ int   s_col[256];
    __shared__ float s_val[256];

    float acc = 0.0f;
    const float* sup = g_support + (size_t)b * N * F_DIM;

    for (int base = start; base < end; base += 256) {
        const int n = min(256, end - base);
        if (tid < n) {
            s_col[tid] = g_col_sorted[base + tid];
            s_val[tid] = g_val_sorted[base + tid];
        }
        __syncthreads();
        for (int e = 0; e < n; e++) {
            acc = fmaf(s_val[e], __ldg(sup + (size_t)s_col[e] * F_DIM + tid), acc);
        }
        __syncthreads();
    }

    out[((size_t)b * N + row) * F_DIM + tid] = fmaxf(acc + bias[tid], 0.0f);
}

extern "C" void kernel_launch(void* const* d_in, const int* in_sizes, int n_in,
                              void* d_out, int out_size) {
    const float* feature_ori = (const float*)d_in[0];
    const float* feature_aug = (const float*)d_in[1];
    const int*   edge_row    = (const int*)d_in[2];
    const int*   edge_col    = (const int*)d_in[3];
    const float* edge_val    = (const float*)d_in[4];
    const float* weight      = (const float*)d_in[5];
    const float* bias        = (const float*)d_in[6];
    float* out = (float*)d_out;

    const int N = in_sizes[0] / D_DIM;   // 50000
    const int E = in_sizes[2];           // 800000

    // CSR build
    zero_deg_kernel<<<(N + 255) / 256, 256>>>(N);
    hist_kernel<<<(E + 255) / 256, 256>>>(edge_row, E);
    scan_kernel<<<1, 1024>>>(N);
    scatter_sort_kernel<<<(E + 255) / 256, 256>>>(edge_row, edge_col, edge_val, E);

    // GEMM -> g_support [2N, F] (fp16x3 HMMA)
    {
        dim3 grid((2 * N + GBM - 1) / GBM, F_DIM / GBN);
        gemm_hmma_kernel<<<grid, 256>>>(feature_ori, feature_aug, weight, N);
    }

    // Aggregate + bias + relu
    {
        dim3 grid(N, 2);
        aggregate_kernel<<<grid, 256>>>(bias, out, N);
    }
}

// round 11
// speedup vs baseline: 2.4503x; 1.4485x over previous
#include <cuda_runtime.h>
#include <cuda_bf16.h>
#include <cuda_fp16.h>
#include <mma.h>
#include <cstdint>

using namespace nvcuda;

#define D_DIM 512
#define F_DIM 256
#define N_MAX 50000
#define E_MAX 800000
// rows padded to a multiple of 128 so the last GEMM tile can store unguarded
#define PAD_ROWS 100096

// Scratch (static device globals — no allocation allowed)
__device__ float g_support[(size_t)PAD_ROWS * F_DIM];   // [>=2N, F] branch-major
__device__ int   g_rowptr[N_MAX + 1];
__device__ int   g_deg[N_MAX];        // zero-initialized at load; re-zeroed by aggregate
__device__ int   g_cursor[N_MAX];
__device__ int   g_col_sorted[E_MAX];
__device__ float g_val_sorted[E_MAX];

// ===========================================================================
// fp16x3 HMMA GEMM: g_support[r][f] = sum_d feat[r][d] * W[d][f]
// r in [0, 2N): r < N -> feature_ori[r], else feature_aug[r-N]
// CTA tile M=128, N=128 (grid.y selects F half), K chunks of 32.
// x = hi + lo (fp16); accumulate hi*hi + hi*lo + lo*hi in fp32 (wmma).
// __launch_bounds__(256,2): 2 CTAs/SM hide staging & conversion latency.
// ===========================================================================
#define GBM 128
#define GBN 128
#define GBK 32
#define A_LD (GBK + 8)     // halves: 40
#define B_LD (GBN + 8)     // halves: 136

__global__ __launch_bounds__(256, 2)
void gemm_hmma_kernel(const float* __restrict__ ori, const float* __restrict__ aug,
                      const float* __restrict__ W, int N) {
    // [split][...] : split 0 = hi, 1 = lo
    __shared__ __align__(16) __half As[2][GBM * A_LD];
    __shared__ __align__(16) __half Bs[2][GBK * B_LD];

    const int tid = threadIdx.x;
    const int wid = tid >> 5;
    const int block_row = blockIdx.x * GBM;
    const int n0 = blockIdx.y * GBN;

    const int warp_m = wid >> 1;   // 0..3 -> 32-row slice
    const int warp_n = wid & 1;    // 0..1 -> 64-col slice

    wmma::fragment<wmma::accumulator, 16, 16, 16, float> acc[2][4];
    #pragma unroll
    for (int i = 0; i < 2; i++)
        #pragma unroll
        for (int j = 0; j < 4; j++) wmma::fill_fragment(acc[i][j], 0.0f);

    for (int k0 = 0; k0 < D_DIM; k0 += GBK) {
        // ---- stage A tile: 128 rows x 32 k (fp32 -> hi/lo fp16) ----
        #pragma unroll
        for (int q = 0; q < 4; q++) {
            const int idx = tid + q * 256;       // 0..1023 float4 slots
            const int r   = idx >> 3;            // 0..127
            const int c4  = (idx & 7) * 4;       // k offset 0..28
            const int grow = block_row + r;
            float4 v = make_float4(0.f, 0.f, 0.f, 0.f);
            if (grow < N)          v = *(const float4*)(ori + (size_t)grow * D_DIM + k0 + c4);
            else if (grow < 2 * N) v = *(const float4*)(aug + (size_t)(grow - N) * D_DIM + k0 + c4);

            __half hx = __float2half_rn(v.x), hy = __float2half_rn(v.y);
            __half hz = __float2half_rn(v.z), hw = __float2half_rn(v.w);
            __half lx = __float2half_rn(v.x - __half2float(hx));
            __half ly = __float2half_rn(v.y - __half2float(hy));
            __half lz = __float2half_rn(v.z - __half2float(hz));
            __half lw = __float2half_rn(v.w - __half2float(hw));

            const int base = r * A_LD + c4;
            *(__half2*)&As[0][base]     = __halves2half2(hx, hy);
            *(__half2*)&As[0][base + 2] = __halves2half2(hz, hw);
            *(__half2*)&As[1][base]     = __halves2half2(lx, ly);
            *(__half2*)&As[1][base + 2] = __halves2half2(lz, lw);
        }
        // ---- stage B tile: 32 k-rows x 128 n (fp32 -> hi/lo fp16) ----
        #pragma unroll
        for (int q = 0; q < 4; q++) {
            const int idx = tid + q * 256;       // 0..1023
            const int kr  = idx >> 5;            // 0..31
            const int c4  = (idx & 31) * 4;      // 0..124
            float4 v = *(const float4*)(W + (size_t)(k0 + kr) * F_DIM + n0 + c4);

            __half hx = __float2half_rn(v.x), hy = __float2half_rn(v.y);
            __half hz = __float2half_rn(v.z), hw = __float2half_rn(v.w);
            __half lx = __float2half_rn(v.x - __half2float(hx));
            __half ly = __float2half_rn(v.y - __half2float(hy));
            __half lz = __float2half_rn(v.z - __half2float(hz));
            __half lw = __float2half_rn(v.w - __half2float(hw));

            const int base = kr * B_LD + c4;
            *(__half2*)&Bs[0][base]     = __halves2half2(hx, hy);
            *(__half2*)&Bs[0][base + 2] = __halves2half2(hz, hw);
            *(__half2*)&Bs[1][base]     = __halves2half2(lx, ly);
            *(__half2*)&Bs[1][base + 2] = __halves2half2(lz, lw);
        }
        __syncthreads();

        // ---- compute: 3 split combos x 2 k-steps x (2m x 4n) wmma ----
        #pragma unroll
        for (int s = 0; s < 3; s++) {
            const int sa = (s == 2) ? 1 : 0;   // (hi,hi), (hi,lo), (lo,hi)
            const int sb = (s == 1) ? 1 : 0;
            #pragma unroll
            for (int kk = 0; kk < GBK; kk += 16) {
                wmma::fragment<wmma::matrix_a, 16, 16, 16, __half, wmma::row_major> a[2];
                #pragma unroll
                for (int i = 0; i < 2; i++)
                    wmma::load_matrix_sync(a[i],
                        &As[sa][(warp_m * 32 + i * 16) * A_LD + kk], A_LD);
                #pragma unroll
                for (int j = 0; j < 4; j++) {
                    wmma::fragment<wmma::matrix_b, 16, 16, 16, __half, wmma::row_major> b;
                    wmma::load_matrix_sync(b,
                        &Bs[sb][kk * B_LD + warp_n * 64 + j * 16], B_LD);
                    #pragma unroll
                    for (int i = 0; i < 2; i++)
                        wmma::mma_sync(acc[i][j], a[i], b, acc[i][j]);
                }
            }
        }
        __syncthreads();
    }

    // ---- store accumulators (rows padded; no bounds check needed) ----
    #pragma unroll
    for (int i = 0; i < 2; i++) {
        const int r = block_row + warp_m * 32 + i * 16;
        #pragma unroll
        for (int j = 0; j < 4; j++) {
            const int c = n0 + warp_n * 64 + j * 16;
            wmma::store_matrix_sync(g_support + (size_t)r * F_DIM + c,
                                    acc[i][j], F_DIM, wmma::mem_row_major);
        }
    }
}

// ---------------------------------------------------------------------------
// CSR build (g_deg is zeroed by the previous call's aggregate_kernel,
// and statically zero on the very first call)
// ---------------------------------------------------------------------------
__global__ void hist_kernel(const int* __restrict__ erow, int E) {
    int e = blockIdx.x * blockDim.x + threadIdx.x;
    if (e < E) atomicAdd(&g_deg[erow[e]], 1);
}

__global__ void scan_kernel(int N) {
    __shared__ int sdata[1024];
    __shared__ int carry;
    const int tid = threadIdx.x;
    if (tid == 0) carry = 0;
    __syncthreads();

    for (int base = 0; base < N; base += 1024) {
        int v = (base + tid < N) ? g_deg[base + tid] : 0;
        sdata[tid] = v;
        __syncthreads();
        #pragma unroll
        for (int off = 1; off < 1024; off <<= 1) {
            int t = (tid >= off) ? sdata[tid - off] : 0;
            __syncthreads();
            sdata[tid] += t;
            __syncthreads();
        }
        int excl = sdata[tid] - v + carry;
        if (base + tid < N) {
            g_rowptr[base + tid] = excl;
            g_cursor[base + tid] = excl;
        }
        __syncthreads();
        if (tid == 1023) carry += sdata[1023];
        __syncthreads();
    }
    if (tid == 0) g_rowptr[N] = carry;
}

__global__ void scatter_sort_kernel(const int* __restrict__ erow,
                                    const int* __restrict__ ecol,
                                    const float* __restrict__ eval_, int E) {
    int e = blockIdx.x * blockDim.x + threadIdx.x;
    if (e >= E) return;
    int r = erow[e];
    int pos = atomicAdd(&g_cursor[r], 1);
    g_col_sorted[pos] = ecol[e];
    g_val_sorted[pos] = eval_[e];
}

// ---------------------------------------------------------------------------
// Aggregate, both branches fused: one block (128 thr) per row.
// threads 0..63  -> branch 0, float4 feature slot (tid&63)
// threads 64..127-> branch 1, same slots
// out[b][row][f] = relu(bias[f] + sum_e val[e] * support[b][col[e]][f])
// Also re-zeros g_deg[row] for the next call.
// ---------------------------------------------------------------------------
__global__ __launch_bounds__(128)
void aggregate_kernel(const float* __restrict__ bias, float* __restrict__ out, int N) {
    const int row = blockIdx.x;
    const int tid = threadIdx.x;
    if (tid == 0) g_deg[row] = 0;     // reset for next kernel_launch call

    const int start = g_rowptr[row];
    const int end   = g_rowptr[row + 1];

    const int grp = tid >> 6;         // branch 0 or 1
    const int f4  = tid & 63;         // float4 slot (feature = f4*4)

    // base pointer: support rows of this branch, offset to this thread's float4
    const float4* sup = (const float4*)(g_support + (size_t)grp * N * F_DIM) + f4;

    __shared__ int   s_col[128];
    __shared__ float s_val[128];

    float4 acc = make_float4(0.f, 0.f, 0.f, 0.f);

    for (int base = start; base < end; base += 128) {
        const int n = min(128, end - base);
        if (tid < n) {
            s_col[tid] = g_col_sorted[base + tid];
            s_val[tid] = g_val_sorted[base + tid];
        }
        __syncthreads();

        int e = 0;
        for (; e + 4 <= n; e += 4) {
            const int   c0 = s_col[e],     c1 = s_col[e + 1];
            const int   c2 = s_col[e + 2], c3 = s_col[e + 3];
            const float v0 = s_val[e],     v1 = s_val[e + 1];
            const float v2 = s_val[e + 2], v3 = s_val[e + 3];
            float4 s0 = __ldg(sup + (size_t)c0 * 64);
            float4 s1 = __ldg(sup + (size_t)c1 * 64);
            float4 s2 = __ldg(sup + (size_t)c2 * 64);
            float4 s3 = __ldg(sup + (size_t)c3 * 64);
            acc.x = fmaf(v0, s0.x, acc.x); acc.y = fmaf(v0, s0.y, acc.y);
            acc.z = fmaf(v0, s0.z, acc.z); acc.w = fmaf(v0, s0.w, acc.w);
            acc.x = fmaf(v1, s1.x, acc.x); acc.y = fmaf(v1, s1.y, acc.y);
            acc.z = fmaf(v1, s1.z, acc.z); acc.w = fmaf(v1, s1.w, acc.w);
            acc.x = fmaf(v2, s2.x, acc.x); acc.y = fmaf(v2, s2.y, acc.y);
            acc.z = fmaf(v2, s2.z, acc.z); acc.w = fmaf(v2, s2.w, acc.w);
            acc.x = fmaf(v3, s3.x, acc.x); acc.y = fmaf(v3, s3.y, acc.y);
            acc.z = fmaf(v3, s3.z, acc.z); acc.w = fmaf(v3, s3.w, acc.w);
        }
        for (; e < n; e++) {
            const int   c = s_col[e];
            const float v = s_val[e];
            float4 s = __ldg(sup + (size_t)c * 64);
            acc.x = fmaf(v, s.x, acc.x); acc.y = fmaf(v, s.y, acc.y);
            acc.z = fmaf(v, s.z, acc.z); acc.w = fmaf(v, s.w, acc.w);
        }
        __syncthreads();
    }

    const float4 bv = *(const float4*)(bias + f4 * 4);
    acc.x = fmaxf(acc.x + bv.x, 0.f);
    acc.y = fmaxf(acc.y + bv.y, 0.f);
    acc.z = fmaxf(acc.z + bv.z, 0.f);
    acc.w = fmaxf(acc.w + bv.w, 0.f);
    *(float4*)(out + ((size_t)grp * N + row) * F_DIM + f4 * 4) = acc;
}

extern "C" void kernel_launch(void* const* d_in, const int* in_sizes, int n_in,
                              void* d_out, int out_size) {
    const float* feature_ori = (const float*)d_in[0];
    const float* feature_aug = (const float*)d_in[1];
    const int*   edge_row    = (const int*)d_in[2];
    const int*   edge_col    = (const int*)d_in[3];
    const float* edge_val    = (const float*)d_in[4];
    const float* weight      = (const float*)d_in[5];
    const float* bias        = (const float*)d_in[6];
    float* out = (float*)d_out;

    const int N = in_sizes[0] / D_DIM;   // 50000
    const int E = in_sizes[2];           // 800000

    // 1) histogram (g_deg zeroed by previous call's aggregate / static init)
    hist_kernel<<<(E + 255) / 256, 256>>>(edge_row, E);
    // 2) exclusive scan -> rowptr, cursor
    scan_kernel<<<1, 1024>>>(N);
    // 3) bucket-sort edges by row
    scatter_sort_kernel<<<(E + 255) / 256, 256>>>(edge_row, edge_col, edge_val, E);
    // 4) GEMM -> g_support [2N, F]   (slot 4: captured by ncu)
    {
        dim3 grid((2 * N + GBM - 1) / GBM, F_DIM / GBN);
        gemm_hmma_kernel<<<grid, 256>>>(feature_ori, feature_aug, weight, N);
    }
    // 5) fused aggregate + bias + relu (also re-zeros g_deg)
    {
        aggregate_kernel<<<N, 128>>>(bias, out, N);
    }
}

// round 12
// speedup vs baseline: 2.4534x; 1.0013x over previous
#include <cuda_runtime.h>
#include <cuda_bf16.h>
#include <cuda_fp16.h>
#include <mma.h>
#include <cstdint>

using namespace nvcuda;

#define D_DIM 512
#define F_DIM 256
#define N_MAX 50000
#define E_MAX 800000
// rows padded to a multiple of 128 so the last GEMM tile can store unguarded
#define PAD_ROWS 100096

// Scratch (static device globals — no allocation allowed)
__device__ float g_support[(size_t)PAD_ROWS * F_DIM];   // [>=2N, F] branch-major
__device__ int   g_rowptr[N_MAX + 1];
__device__ int   g_deg[N_MAX];        // zero-initialized at load; re-zeroed by aggregate
__device__ int   g_cursor[N_MAX];
__device__ int   g_col_sorted[E_MAX];
__device__ float g_val_sorted[E_MAX];

// ===========================================================================
// fp16x3 HMMA GEMM: g_support[r][f] = sum_d feat[r][d] * W[d][f]
// r in [0, 2N): r < N -> feature_ori[r], else feature_aug[r-N]
// CTA tile M=128, N=128 (grid.y selects F half), K chunks of 32.
// x = hi + lo (fp16); accumulate hi*hi + hi*lo + lo*hi in fp32 (wmma).
// __launch_bounds__(256,2): 2 CTAs/SM hide staging & conversion latency.
// ===========================================================================
#define GBM 128
#define GBN 128
#define GBK 32
#define A_LD (GBK + 8)     // halves: 40
#define B_LD (GBN + 8)     // halves: 136

__global__ __launch_bounds__(256, 2)
void gemm_hmma_kernel(const float* __restrict__ ori, const float* __restrict__ aug,
                      const float* __restrict__ W, int N) {
    // [split][...] : split 0 = hi, 1 = lo
    __shared__ __align__(16) __half As[2][GBM * A_LD];
    __shared__ __align__(16) __half Bs[2][GBK * B_LD];

    const int tid = threadIdx.x;
    const int wid = tid >> 5;
    const int block_row = blockIdx.x * GBM;
    const int n0 = blockIdx.y * GBN;

    const int warp_m = wid >> 1;   // 0..3 -> 32-row slice
    const int warp_n = wid & 1;    // 0..1 -> 64-col slice

    wmma::fragment<wmma::accumulator, 16, 16, 16, float> acc[2][4];
    #pragma unroll
    for (int i = 0; i < 2; i++)
        #pragma unroll
        for (int j = 0; j < 4; j++) wmma::fill_fragment(acc[i][j], 0.0f);

    for (int k0 = 0; k0 < D_DIM; k0 += GBK) {
        // ---- stage A tile: 128 rows x 32 k (fp32 -> hi/lo fp16) ----
        #pragma unroll
        for (int q = 0; q < 4; q++) {
            const int idx = tid + q * 256;       // 0..1023 float4 slots
            const int r   = idx >> 3;            // 0..127
            const int c4  = (idx & 7) * 4;       // k offset 0..28
            const int grow = block_row + r;
            float4 v = make_float4(0.f, 0.f, 0.f, 0.f);
            if (grow < N)          v = *(const float4*)(ori + (size_t)grow * D_DIM + k0 + c4);
            else if (grow < 2 * N) v = *(const float4*)(aug + (size_t)(grow - N) * D_DIM + k0 + c4);

            __half hx = __float2half_rn(v.x), hy = __float2half_rn(v.y);
            __half hz = __float2half_rn(v.z), hw = __float2half_rn(v.w);
            __half lx = __float2half_rn(v.x - __half2float(hx));
            __half ly = __float2half_rn(v.y - __half2float(hy));
            __half lz = __float2half_rn(v.z - __half2float(hz));
            __half lw = __float2half_rn(v.w - __half2float(hw));

            const int base = r * A_LD + c4;
            *(__half2*)&As[0][base]     = __halves2half2(hx, hy);
            *(__half2*)&As[0][base + 2] = __halves2half2(hz, hw);
            *(__half2*)&As[1][base]     = __halves2half2(lx, ly);
            *(__half2*)&As[1][base + 2] = __halves2half2(lz, lw);
        }
        // ---- stage B tile: 32 k-rows x 128 n (fp32 -> hi/lo fp16) ----
        #pragma unroll
        for (int q = 0; q < 4; q++) {
            const int idx = tid + q * 256;       // 0..1023
            const int kr  = idx >> 5;            // 0..31
            const int c4  = (idx & 31) * 4;      // 0..124
            float4 v = *(const float4*)(W + (size_t)(k0 + kr) * F_DIM + n0 + c4);

            __half hx = __float2half_rn(v.x), hy = __float2half_rn(v.y);
            __half hz = __float2half_rn(v.z), hw = __float2half_rn(v.w);
            __half lx = __float2half_rn(v.x - __half2float(hx));
            __half ly = __float2half_rn(v.y - __half2float(hy));
            __half lz = __float2half_rn(v.z - __half2float(hz));
            __half lw = __float2half_rn(v.w - __half2float(hw));

            const int base = kr * B_LD + c4;
            *(__half2*)&Bs[0][base]     = __halves2half2(hx, hy);
            *(__half2*)&Bs[0][base + 2] = __halves2half2(hz, hw);
            *(__half2*)&Bs[1][base]     = __halves2half2(lx, ly);
            *(__half2*)&Bs[1][base + 2] = __halves2half2(lz, lw);
        }
        __syncthreads();

        // ---- compute: 3 split combos x 2 k-steps x (2m x 4n) wmma ----
        #pragma unroll
        for (int s = 0; s < 3; s++) {
            const int sa = (s == 2) ? 1 : 0;   // (hi,hi), (hi,lo), (lo,hi)
            const int sb = (s == 1) ? 1 : 0;
            #pragma unroll
            for (int kk = 0; kk < GBK; kk += 16) {
                wmma::fragment<wmma::matrix_a, 16, 16, 16, __half, wmma::row_major> a[2];
                #pragma unroll
                for (int i = 0; i < 2; i++)
                    wmma::load_matrix_sync(a[i],
                        &As[sa][(warp_m * 32 + i * 16) * A_LD + kk], A_LD);
                #pragma unroll
                for (int j = 0; j < 4; j++) {
                    wmma::fragment<wmma::matrix_b, 16, 16, 16, __half, wmma::row_major> b;
                    wmma::load_matrix_sync(b,
                        &Bs[sb][kk * B_LD + warp_n * 64 + j * 16], B_LD);
                    #pragma unroll
                    for (int i = 0; i < 2; i++)
                        wmma::mma_sync(acc[i][j], a[i], b, acc[i][j]);
                }
            }
        }
        __syncthreads();
    }

    // ---- store accumulators (rows padded; no bounds check needed) ----
    #pragma unroll
    for (int i = 0; i < 2; i++) {
        const int r = block_row + warp_m * 32 + i * 16;
        #pragma unroll
        for (int j = 0; j < 4; j++) {
            const int c = n0 + warp_n * 64 + j * 16;
            wmma::store_matrix_sync(g_support + (size_t)r * F_DIM + c,
                                    acc[i][j], F_DIM, wmma::mem_row_major);
        }
    }
}

// ---------------------------------------------------------------------------
// CSR build (g_deg is zeroed by the previous call's aggregate_kernel,
// and statically zero on the very first call)
// ---------------------------------------------------------------------------
__global__ void hist_kernel(const int* __restrict__ erow, int E) {
    int e = blockIdx.x * blockDim.x + threadIdx.x;
    if (e < E) atomicAdd(&g_deg[erow[e]], 1);
}

__global__ void scan_kernel(int N) {
    __shared__ int sdata[1024];
    __shared__ int carry;
    const int tid = threadIdx.x;
    if (tid == 0) carry = 0;
    __syncthreads();

    for (int base = 0; base < N; base += 1024) {
        int v = (base + tid < N) ? g_deg[base + tid] : 0;
        sdata[tid] = v;
        __syncthreads();
        #pragma unroll
        for (int off = 1; off < 1024; off <<= 1) {
            int t = (tid >= off) ? sdata[tid - off] : 0;
            __syncthreads();
            sdata[tid] += t;
            __syncthreads();
        }
        int excl = sdata[tid] - v + carry;
        if (base + tid < N) {
            g_rowptr[base + tid] = excl;
            g_cursor[base + tid] = excl;
        }
        __syncthreads();
        if (tid == 1023) carry += sdata[1023];
        __syncthreads();
    }
    if (tid == 0) g_rowptr[N] = carry;
}

__global__ void scatter_sort_kernel(const int* __restrict__ erow,
                                    const int* __restrict__ ecol,
                                    const float* __restrict__ eval_, int E) {
    int e = blockIdx.x * blockDim.x + threadIdx.x;
    if (e >= E) return;
    int r = erow[e];
    int pos = atomicAdd(&g_cursor[r], 1);
    g_col_sorted[pos] = ecol[e];
    g_val_sorted[pos] = eval_[e];
}

// ---------------------------------------------------------------------------
// Aggregate, both branches fused: one block (128 thr) per row.
// threads 0..63  -> branch 0, float4 feature slot (tid&63)
// threads 64..127-> branch 1, same slots
// out[b][row][f] = relu(bias[f] + sum_e val[e] * support[b][col[e]][f])
// Also re-zeros g_deg[row] for the next call.
// ---------------------------------------------------------------------------
__global__ __launch_bounds__(128)
void aggregate_kernel(const float* __restrict__ bias, float* __restrict__ out, int N) {
    const int row = blockIdx.x;
    const int tid = threadIdx.x;
    if (tid == 0) g_deg[row] = 0;     // reset for next kernel_launch call

    const int start = g_rowptr[row];
    const int end   = g_rowptr[row + 1];

    const int grp = tid >> 6;         // branch 0 or 1
    const int f4  = tid & 63;         // float4 slot (feature = f4*4)

    // base pointer: support rows of this branch, offset to this thread's float4
    const float4* sup = (const float4*)(g_support + (size_t)grp * N * F_DIM) + f4;

    __shared__ int   s_col[128];
    __shared__ float s_val[128];

    float4 acc = make_float4(0.f, 0.f, 0.f, 0.f);

    for (int base = start; base < end; base += 128) {
        const int n = min(128, end - base);
        if (tid < n) {
            s_col[tid] = g_col_sorted[base + tid];
            s_val[tid] = g_val_sorted[base + tid];
        }
        __syncthreads();

        int e = 0;
        for (; e + 4 <= n; e += 4) {
            const int   c0 = s_col[e],     c1 = s_col[e + 1];
            const int   c2 = s_col[e + 2], c3 = s_col[e + 3];
            const float v0 = s_val[e],     v1 = s_val[e + 1];
            const float v2 = s_val[e + 2], v3 = s_val[e + 3];
            float4 s0 = __ldg(sup + (size_t)c0 * 64);
            float4 s1 = __ldg(sup + (size_t)c1 * 64);
            float4 s2 = __ldg(sup + (size_t)c2 * 64);
            float4 s3 = __ldg(sup + (size_t)c3 * 64);
            acc.x = fmaf(v0, s0.x, acc.x); acc.y = fmaf(v0, s0.y, acc.y);
            acc.z = fmaf(v0, s0.z, acc.z); acc.w = fmaf(v0, s0.w, acc.w);
            acc.x = fmaf(v1, s1.x, acc.x); acc.y = fmaf(v1, s1.y, acc.y);
            acc.z = fmaf(v1, s1.z, acc.z); acc.w = fmaf(v1, s1.w, acc.w);
            acc.x = fmaf(v2, s2.x, acc.x); acc.y = fmaf(v2, s2.y, acc.y);
            acc.z = fmaf(v2, s2.z, acc.z); acc.w = fmaf(v2, s2.w, acc.w);
            acc.x = fmaf(v3, s3.x, acc.x); acc.y = fmaf(v3, s3.y, acc.y);
            acc.z = fmaf(v3, s3.z, acc.z); acc.w = fmaf(v3, s3.w, acc.w);
        }
        for (; e < n; e++) {
            const int   c = s_col[e];
            const float v = s_val[e];
            float4 s = __ldg(sup + (size_t)c * 64);
            acc.x = fmaf(v, s.x, acc.x); acc.y = fmaf(v, s.y, acc.y);
            acc.z = fmaf(v, s.z, acc.z); acc.w = fmaf(v, s.w, acc.w);
        }
        __syncthreads();
    }

    const float4 bv = *(const float4*)(bias + f4 * 4);
    acc.x = fmaxf(acc.x + bv.x, 0.f);
    acc.y = fmaxf(acc.y + bv.y, 0.f);
    acc.z = fmaxf(acc.z + bv.z, 0.f);
    acc.w = fmaxf(acc.w + bv.w, 0.f);
    *(float4*)(out + ((size_t)grp * N + row) * F_DIM + f4 * 4) = acc;
}

extern "C" void kernel_launch(void* const* d_in, const int* in_sizes, int n_in,
                              void* d_out, int out_size) {
    const float* feature_ori = (const float*)d_in[0];
    const float* feature_aug = (const float*)d_in[1];
    const int*   edge_row    = (const int*)d_in[2];
    const int*   edge_col    = (const int*)d_in[3];
    const float* edge_val    = (const float*)d_in[4];
    const float* weight      = (const float*)d_in[5];
    const float* bias        = (const float*)d_in[6];
    float* out = (float*)d_out;

    const int N = in_sizes[0] / D_DIM;   // 50000
    const int E = in_sizes[2];           // 800000

    // 1) histogram (g_deg zeroed by previous call's aggregate / static init)
    hist_kernel<<<(E + 255) / 256, 256>>>(edge_row, E);
    // 2) exclusive scan -> rowptr, cursor
    scan_kernel<<<1, 1024>>>(N);
    // 3) bucket-sort edges by row
    scatter_sort_kernel<<<(E + 255) / 256, 256>>>(edge_row, edge_col, edge_val, E);
    // 4) GEMM -> g_support [2N, F]   (slot 4: captured by ncu)
    {
        dim3 grid((2 * N + GBM - 1) / GBM, F_DIM / GBN);
        gemm_hmma_kernel<<<grid, 256>>>(feature_ori, feature_aug, weight, N);
    }
    // 5) fused aggregate + bias + relu (also re-zeros g_deg)
    {
        aggregate_kernel<<<N, 128>>>(bias, out, N);
    }
}